// round 2
// baseline (speedup 1.0000x reference)
#include <cuda_runtime.h>
#include <cstdint>

#define HW      409600      // 640*640
#define NCH     12
#define NB      8
#define NCLS    2
#define NINST   16          // NCLS * NB
#define NMAPS   6
#define EPSF    1e-4f
#define LAMBDAF 0.7f

// ---------------- scratch (static device globals; no allocation) ------------
__device__ unsigned int g_keys[(size_t)NINST * HW];   // ~26 MB
__device__ unsigned int g_hist[NINST][256];
__device__ unsigned int g_pos[NINST];
__device__ unsigned int g_negtot[NINST];
__device__ unsigned int g_prefix[NINST];
__device__ unsigned int g_k[NINST];
__device__ float        g_thr[NINST];
__device__ int          g_fallback[NINST];
__device__ float        g_sums[NINST][18];            // [0..2]=text a,b,c ; [3+3c..]=kernel c

// ---------------- helpers ---------------------------------------------------
__device__ __forceinline__ unsigned int order_key(float x) {
    unsigned int u = __float_as_uint(x);
    u = (u & 0x80000000u) ? ~u : (u | 0x80000000u);
    if (u == 0u) u = 1u;   // reserve 0 as "not a negative" sentinel (only -NaN maps here)
    return u;
}
__device__ __forceinline__ float key_to_float(unsigned int k) {
    unsigned int bits = (k & 0x80000000u) ? (k ^ 0x80000000u) : ~k;
    return __uint_as_float(bits);
}
__device__ __forceinline__ float sigmoidf_fast(float x) {
    return 1.0f / (1.0f + __expf(-x));
}

// ---------------- kernels ---------------------------------------------------
__global__ void zero_kernel() {
    int inst = blockIdx.x, t = threadIdx.x;
    g_hist[inst][t] = 0u;
    if (t < 18) g_sums[inst][t] = 0.0f;
    if (t == 0) {
        g_pos[inst] = 0u; g_negtot[inst] = 0u;
        g_prefix[inst] = 0u; g_k[inst] = 0u; g_fallback[inst] = 0;
    }
}

// Pass 0: build keys for negatives, count pos/neg, histogram top byte.
__global__ void pass0_kernel(const float* __restrict__ outputs,
                             const float* __restrict__ labels,
                             const float* __restrict__ tmask) {
    const int inst = blockIdx.y;
    const int cls  = inst >> 3, b = inst & 7;
    const int ch   = cls * NMAPS + (NMAPS - 1);
    const float* __restrict__ s = outputs + ((size_t)b * NCH + ch) * HW;
    const float* __restrict__ g = labels  + ((size_t)b * NCH + ch) * HW;
    const float* __restrict__ m = tmask   + (size_t)b * HW;
    unsigned int* __restrict__ keys = g_keys + (size_t)inst * HW;

    __shared__ unsigned int hist[256];
    __shared__ unsigned int spos, sneg;
    for (int i = threadIdx.x; i < 256; i += blockDim.x) hist[i] = 0u;
    if (threadIdx.x == 0) { spos = 0u; sneg = 0u; }
    __syncthreads();

    unsigned int lpos = 0, lneg = 0;
    for (int p = blockIdx.x * blockDim.x + threadIdx.x; p < HW;
         p += gridDim.x * blockDim.x) {
        float gv = g[p], sv = s[p], mv = m[p];
        unsigned int key = 0u;
        if (gv <= 0.5f) {
            key = order_key(sv);
            atomicAdd(&hist[key >> 24], 1u);
            lneg++;
        } else if (mv > 0.5f) {
            lpos++;
        }
        keys[p] = key;
    }
    atomicAdd(&spos, lpos);
    atomicAdd(&sneg, lneg);
    __syncthreads();
    for (int i = threadIdx.x; i < 256; i += blockDim.x)
        if (hist[i]) atomicAdd(&g_hist[inst][i], hist[i]);
    if (threadIdx.x == 0) {
        if (spos) atomicAdd(&g_pos[inst], spos);
        if (sneg) atomicAdd(&g_negtot[inst], sneg);
    }
}

// Consume histogram for this radix pass, pick byte, update prefix & k, zero hist.
__global__ void select_kernel(int pass) {
    const int inst = blockIdx.x;
    __shared__ unsigned int h[256];
    h[threadIdx.x] = g_hist[inst][threadIdx.x];
    __syncthreads();
    g_hist[inst][threadIdx.x] = 0u;   // ready for next pass
    if (threadIdx.x == 0) {
        const int shift = 24 - 8 * pass;
        unsigned int k;
        if (pass == 0) {
            unsigned int pos = g_pos[inst], negt = g_negtot[inst];
            unsigned long long nn = (unsigned long long)pos * 3ull;
            unsigned int neg_num = (unsigned int)(nn < (unsigned long long)negt ? nn
                                                                                : (unsigned long long)negt);
            int fb = (pos == 0u) || (neg_num == 0u);
            g_fallback[inst] = fb;
            k = fb ? 1u : neg_num;
        } else {
            k = g_k[inst];
        }
        unsigned int cum = 0; int found = -1;
        for (int bin = 255; bin >= 0; --bin) {
            if (cum + h[bin] >= k) { found = bin; break; }
            cum += h[bin];
        }
        if (found < 0) found = 0;   // only reachable in fallback (hist empty)
        g_prefix[inst] |= ((unsigned int)found) << shift;
        g_k[inst] = k - cum;
        if (pass == 3) g_thr[inst] = key_to_float(g_prefix[inst]);
    }
}

// Radix passes 1..3: histogram next byte among keys matching the current prefix.
__global__ void hist_kernel(int shift) {
    const int inst = blockIdx.y;
    const unsigned int* __restrict__ keys = g_keys + (size_t)inst * HW;
    const int hishift = shift + 8;
    const unsigned int pfx = g_prefix[inst] >> hishift;

    __shared__ unsigned int hist[256];
    for (int i = threadIdx.x; i < 256; i += blockDim.x) hist[i] = 0u;
    __syncthreads();

    for (int p = blockIdx.x * blockDim.x + threadIdx.x; p < HW;
         p += gridDim.x * blockDim.x) {
        unsigned int key = keys[p];
        if (key != 0u && (key >> hishift) == pfx)
            atomicAdd(&hist[(key >> shift) & 0xFFu], 1u);
    }
    __syncthreads();
    for (int i = threadIdx.x; i < 256; i += blockDim.x)
        if (hist[i]) atomicAdd(&g_hist[inst][i], hist[i]);
}

// Fused dice-sum pass over text channel + 5 kernel channels per instance.
__global__ void dice_kernel(const float* __restrict__ outputs,
                            const float* __restrict__ labels,
                            const float* __restrict__ tmask) {
    const int inst = blockIdx.y;
    const int cls  = inst >> 3, b = inst & 7;
    const int ctxt = cls * NMAPS + (NMAPS - 1);
    const float* __restrict__ txt = outputs + ((size_t)b * NCH + ctxt) * HW;
    const float* __restrict__ gtx = labels  + ((size_t)b * NCH + ctxt) * HW;
    const float* __restrict__ m   = tmask   + (size_t)b * HW;
    const float* __restrict__ ker = outputs + ((size_t)b * NCH + cls * NMAPS) * HW;
    const float* __restrict__ gk  = labels  + ((size_t)b * NCH + cls * NMAPS) * HW;

    const float thr = g_thr[inst];
    const int   fb  = g_fallback[inst];

    float acc[18];
#pragma unroll
    for (int j = 0; j < 18; j++) acc[j] = 0.0f;

    __shared__ float ssum[18];
    if (threadIdx.x < 18) ssum[threadIdx.x] = 0.0f;
    __syncthreads();

    for (int p = blockIdx.x * blockDim.x + threadIdx.x; p < HW;
         p += gridDim.x * blockDim.x) {
        float sv = txt[p], gv = gtx[p], mv = m[p];
        float sel;
        if (fb) sel = mv;
        else    sel = (((sv >= thr) || (gv > 0.5f)) && (mv > 0.5f)) ? 1.0f : 0.0f;
        float sig = sigmoidf_fast(sv);
        float pp = sig * sel, tt = gv * sel;
        acc[0] += pp * tt; acc[1] += pp * pp; acc[2] += tt * tt;

        float selk = ((sv > 0.0f) && (mv > 0.5f)) ? 1.0f : 0.0f;
#pragma unroll
        for (int c = 0; c < NMAPS - 1; c++) {
            float kv  = ker[(size_t)c * HW + p];
            float gkv = gk [(size_t)c * HW + p];
            float sk  = sigmoidf_fast(kv);
            float p2 = sk * selk, t2 = gkv * selk;
            acc[3 + c * 3] += p2 * t2;
            acc[4 + c * 3] += p2 * p2;
            acc[5 + c * 3] += t2 * t2;
        }
    }

    const int lane = threadIdx.x & 31;
#pragma unroll
    for (int j = 0; j < 18; j++) {
        float v = acc[j];
#pragma unroll
        for (int off = 16; off > 0; off >>= 1)
            v += __shfl_down_sync(0xFFFFFFFFu, v, off);
        if (lane == 0) atomicAdd(&ssum[j], v);
    }
    __syncthreads();
    if (threadIdx.x < 18)
        atomicAdd(&g_sums[inst][threadIdx.x], ssum[threadIdx.x]);
}

__global__ void finalize_kernel(float* __restrict__ out) {
    if (threadIdx.x != 0 || blockIdx.x != 0) return;
    float lt_sum = 0.f, lk_sum = 0.f, loss_sum = 0.f;
    for (int cls = 0; cls < NCLS; cls++) {
        float lt = 0.f, lk = 0.f;
        for (int b = 0; b < NB; b++) {
            const float* s = g_sums[cls * NB + b];
            float a  = s[0], bb = s[1] + EPSF, cc = s[2] + EPSF;
            lt += 1.f - 2.f * a / (bb + cc);
            float lkb = 0.f;
            for (int c = 0; c < NMAPS - 1; c++) {
                float a2 = s[3 + c * 3], b2 = s[4 + c * 3] + EPSF, c2 = s[5 + c * 3] + EPSF;
                lkb += 1.f - 2.f * a2 / (b2 + c2);
            }
            lk += lkb / (float)(NMAPS - 1);
        }
        lt /= (float)NB; lk /= (float)NB;
        lt_sum += lt; lk_sum += lk;
        loss_sum += LAMBDAF * lt + (1.f - LAMBDAF) * lk;
    }
    out[0] = loss_sum / (float)NCLS;
    out[1] = lt_sum   / (float)NCLS;
    out[2] = lk_sum   / (float)NCLS;
}

// ---------------- launch -----------------------------------------------------
extern "C" void kernel_launch(void* const* d_in, const int* in_sizes, int n_in,
                              void* d_out, int out_size) {
    const float* outputs = (const float*)d_in[0];
    const float* labels  = (const float*)d_in[1];
    const float* tmask   = (const float*)d_in[2];
    float* out = (float*)d_out;

    zero_kernel<<<NINST, 256>>>();
    pass0_kernel<<<dim3(128, NINST), 256>>>(outputs, labels, tmask);
    select_kernel<<<NINST, 256>>>(0);
    hist_kernel<<<dim3(64, NINST), 256>>>(16);
    select_kernel<<<NINST, 256>>>(1);
    hist_kernel<<<dim3(64, NINST), 256>>>(8);
    select_kernel<<<NINST, 256>>>(2);
    hist_kernel<<<dim3(64, NINST), 256>>>(0);
    select_kernel<<<NINST, 256>>>(3);
    dice_kernel<<<dim3(192, NINST), 256>>>(outputs, labels, tmask);
    finalize_kernel<<<1, 32>>>(out);
}

// round 3
// speedup vs baseline: 1.7521x; 1.7521x over previous
#include <cuda_runtime.h>
#include <cstdint>

#define HW      409600      // 640*640
#define NVEC    (HW/4)      // 102400
#define NCH     12
#define NB      8
#define NCLS    2
#define NINST   16          // NCLS * NB
#define NMAPS   6
#define EPSF    1e-4f
#define LAMBDAF 0.7f

// ---------------- scratch (static device globals; no allocation) ------------
__device__ unsigned int g_keys[(size_t)NINST * HW];   // ~26 MB
__device__ unsigned int g_hist[NINST][256];
__device__ unsigned int g_pos[NINST];
__device__ unsigned int g_negtot[NINST];
__device__ unsigned int g_prefix[NINST];
__device__ unsigned int g_k[NINST];
__device__ float        g_thr[NINST];
__device__ int          g_fallback[NINST];
__device__ float        g_sums[NINST][18];

// ---------------- helpers ---------------------------------------------------
__device__ __forceinline__ unsigned int order_key(float x) {
    unsigned int u = __float_as_uint(x);
    u = (u & 0x80000000u) ? ~u : (u | 0x80000000u);
    if (u == 0u) u = 1u;   // reserve 0 as "not a negative" sentinel
    return u;
}
__device__ __forceinline__ float key_to_float(unsigned int k) {
    unsigned int bits = (k & 0x80000000u) ? (k ^ 0x80000000u) : ~k;
    return __uint_as_float(bits);
}
__device__ __forceinline__ float sigmoidf_fast(float x) {
    return 1.0f / (1.0f + __expf(-x));
}

// ---------------- kernels ---------------------------------------------------
__global__ void zero_kernel() {
    int inst = blockIdx.x, t = threadIdx.x;
    g_hist[inst][t] = 0u;
    if (t < 18) g_sums[inst][t] = 0.0f;
    if (t == 0) {
        g_pos[inst] = 0u; g_negtot[inst] = 0u;
        g_prefix[inst] = 0u; g_k[inst] = 0u; g_fallback[inst] = 0;
    }
}

// Pass 0 (vectorized): build keys for negatives, count pos/neg, hist top byte.
__global__ void pass0_kernel(const float* __restrict__ outputs,
                             const float* __restrict__ labels,
                             const float* __restrict__ tmask) {
    const int inst = blockIdx.y;
    const int cls  = inst >> 3, b = inst & 7;
    const int ch   = cls * NMAPS + (NMAPS - 1);
    const float4* __restrict__ s4 = (const float4*)(outputs + ((size_t)b * NCH + ch) * HW);
    const float4* __restrict__ g4 = (const float4*)(labels  + ((size_t)b * NCH + ch) * HW);
    const float4* __restrict__ m4 = (const float4*)(tmask   + (size_t)b * HW);
    uint4* __restrict__ keys4 = (uint4*)(g_keys + (size_t)inst * HW);

    __shared__ unsigned int hist[256];
    __shared__ unsigned int spos, sneg;
    for (int i = threadIdx.x; i < 256; i += blockDim.x) hist[i] = 0u;
    if (threadIdx.x == 0) { spos = 0u; sneg = 0u; }
    __syncthreads();

    unsigned int lpos = 0, lneg = 0;
    for (int v = blockIdx.x * blockDim.x + threadIdx.x; v < NVEC;
         v += gridDim.x * blockDim.x) {
        float4 gv = g4[v], sv = s4[v], mv = m4[v];
        uint4 k; k.x = 0u; k.y = 0u; k.z = 0u; k.w = 0u;
        const float* gp = &gv.x; const float* sp = &sv.x; const float* mp = &mv.x;
        unsigned int* kp = &k.x;
#pragma unroll
        for (int j = 0; j < 4; j++) {
            if (gp[j] <= 0.5f) {
                unsigned int key = order_key(sp[j]);
                kp[j] = key;
                atomicAdd(&hist[key >> 24], 1u);
                lneg++;
            } else if (mp[j] > 0.5f) {
                lpos++;
            }
        }
        keys4[v] = k;
    }
    atomicAdd(&spos, lpos);
    atomicAdd(&sneg, lneg);
    __syncthreads();
    for (int i = threadIdx.x; i < 256; i += blockDim.x)
        if (hist[i]) atomicAdd(&g_hist[inst][i], hist[i]);
    if (threadIdx.x == 0) {
        if (spos) atomicAdd(&g_pos[inst], spos);
        if (sneg) atomicAdd(&g_negtot[inst], sneg);
    }
}

// Consume histogram for this radix pass, pick byte, update prefix & k, zero hist.
__global__ void select_kernel(int pass) {
    const int inst = blockIdx.x;
    __shared__ unsigned int h[256];
    h[threadIdx.x] = g_hist[inst][threadIdx.x];
    __syncthreads();
    g_hist[inst][threadIdx.x] = 0u;   // ready for next pass
    if (threadIdx.x == 0) {
        const int shift = 24 - 8 * pass;
        unsigned int k;
        if (pass == 0) {
            unsigned int pos = g_pos[inst], negt = g_negtot[inst];
            unsigned long long nn = (unsigned long long)pos * 3ull;
            unsigned int neg_num = (unsigned int)(nn < (unsigned long long)negt ? nn
                                                                                : (unsigned long long)negt);
            int fb = (pos == 0u) || (neg_num == 0u);
            g_fallback[inst] = fb;
            k = fb ? 1u : neg_num;
        } else {
            k = g_k[inst];
        }
        unsigned int cum = 0; int found = -1;
        for (int bin = 255; bin >= 0; --bin) {
            if (cum + h[bin] >= k) { found = bin; break; }
            cum += h[bin];
        }
        if (found < 0) found = 0;
        g_prefix[inst] |= ((unsigned int)found) << shift;
        g_k[inst] = k - cum;
        if (pass == 3) g_thr[inst] = key_to_float(g_prefix[inst]);
    }
}

// Radix passes 1..3 (vectorized uint4 read of L2-resident key buffer).
__global__ void hist_kernel(int shift) {
    const int inst = blockIdx.y;
    const uint4* __restrict__ keys4 = (const uint4*)(g_keys + (size_t)inst * HW);
    const int hishift = shift + 8;
    const unsigned int pfx = g_prefix[inst] >> hishift;

    __shared__ unsigned int hist[256];
    for (int i = threadIdx.x; i < 256; i += blockDim.x) hist[i] = 0u;
    __syncthreads();

    for (int v = blockIdx.x * blockDim.x + threadIdx.x; v < NVEC;
         v += gridDim.x * blockDim.x) {
        uint4 k = keys4[v];
        const unsigned int* kp = &k.x;
#pragma unroll
        for (int j = 0; j < 4; j++) {
            unsigned int key = kp[j];
            if (key != 0u && (key >> hishift) == pfx)
                atomicAdd(&hist[(key >> shift) & 0xFFu], 1u);
        }
    }
    __syncthreads();
    for (int i = threadIdx.x; i < 256; i += blockDim.x)
        if (hist[i]) atomicAdd(&g_hist[inst][i], hist[i]);
}

// Fused dice-sum pass (vectorized): text + 5 kernel channels per instance.
__global__ void __launch_bounds__(256) dice_kernel(
        const float* __restrict__ outputs,
        const float* __restrict__ labels,
        const float* __restrict__ tmask) {
    const int inst = blockIdx.y;
    const int cls  = inst >> 3, b = inst & 7;
    const int ctxt = cls * NMAPS + (NMAPS - 1);
    const float4* __restrict__ txt4 = (const float4*)(outputs + ((size_t)b * NCH + ctxt) * HW);
    const float4* __restrict__ gtx4 = (const float4*)(labels  + ((size_t)b * NCH + ctxt) * HW);
    const float4* __restrict__ m4   = (const float4*)(tmask   + (size_t)b * HW);
    const float4* __restrict__ ker4 = (const float4*)(outputs + ((size_t)b * NCH + cls * NMAPS) * HW);
    const float4* __restrict__ gk4  = (const float4*)(labels  + ((size_t)b * NCH + cls * NMAPS) * HW);

    const float thr = g_thr[inst];
    const int   fb  = g_fallback[inst];

    float acc[18];
#pragma unroll
    for (int j = 0; j < 18; j++) acc[j] = 0.0f;

    __shared__ float ssum[18];
    if (threadIdx.x < 18) ssum[threadIdx.x] = 0.0f;
    __syncthreads();

    for (int v = blockIdx.x * blockDim.x + threadIdx.x; v < NVEC;
         v += gridDim.x * blockDim.x) {
        // front-batch all 13 LDG.128s for maximum MLP
        float4 sv4 = txt4[v];
        float4 gv4 = gtx4[v];
        float4 mv4 = m4[v];
        float4 kv4[NMAPS - 1], gkv4[NMAPS - 1];
#pragma unroll
        for (int c = 0; c < NMAPS - 1; c++) {
            kv4[c]  = ker4[(size_t)c * NVEC + v];
            gkv4[c] = gk4 [(size_t)c * NVEC + v];
        }

        const float* sv = &sv4.x; const float* gv = &gv4.x; const float* mv = &mv4.x;
#pragma unroll
        for (int j = 0; j < 4; j++) {
            float s = sv[j], g = gv[j], m = mv[j];
            float sel;
            if (fb) sel = m;
            else    sel = (((s >= thr) || (g > 0.5f)) && (m > 0.5f)) ? 1.0f : 0.0f;
            float sig = sigmoidf_fast(s);
            float pp = sig * sel, tt = g * sel;
            acc[0] += pp * tt; acc[1] += pp * pp; acc[2] += tt * tt;

            float selk = ((s > 0.0f) && (m > 0.5f)) ? 1.0f : 0.0f;
#pragma unroll
            for (int c = 0; c < NMAPS - 1; c++) {
                float kv  = (&kv4[c].x)[j];
                float gkv = (&gkv4[c].x)[j];
                float sk  = sigmoidf_fast(kv);
                float p2 = sk * selk, t2 = gkv * selk;
                acc[3 + c * 3] += p2 * t2;
                acc[4 + c * 3] += p2 * p2;
                acc[5 + c * 3] += t2 * t2;
            }
        }
    }

    const int lane = threadIdx.x & 31;
#pragma unroll
    for (int j = 0; j < 18; j++) {
        float vv = acc[j];
#pragma unroll
        for (int off = 16; off > 0; off >>= 1)
            vv += __shfl_down_sync(0xFFFFFFFFu, vv, off);
        if (lane == 0) atomicAdd(&ssum[j], vv);
    }
    __syncthreads();
    if (threadIdx.x < 18)
        atomicAdd(&g_sums[inst][threadIdx.x], ssum[threadIdx.x]);
}

__global__ void finalize_kernel(float* __restrict__ out) {
    if (threadIdx.x != 0 || blockIdx.x != 0) return;
    float lt_sum = 0.f, lk_sum = 0.f, loss_sum = 0.f;
    for (int cls = 0; cls < NCLS; cls++) {
        float lt = 0.f, lk = 0.f;
        for (int b = 0; b < NB; b++) {
            const float* s = g_sums[cls * NB + b];
            float a  = s[0], bb = s[1] + EPSF, cc = s[2] + EPSF;
            lt += 1.f - 2.f * a / (bb + cc);
            float lkb = 0.f;
            for (int c = 0; c < NMAPS - 1; c++) {
                float a2 = s[3 + c * 3], b2 = s[4 + c * 3] + EPSF, c2 = s[5 + c * 3] + EPSF;
                lkb += 1.f - 2.f * a2 / (b2 + c2);
            }
            lk += lkb / (float)(NMAPS - 1);
        }
        lt /= (float)NB; lk /= (float)NB;
        lt_sum += lt; lk_sum += lk;
        loss_sum += LAMBDAF * lt + (1.f - LAMBDAF) * lk;
    }
    out[0] = loss_sum / (float)NCLS;
    out[1] = lt_sum   / (float)NCLS;
    out[2] = lk_sum   / (float)NCLS;
}

// ---------------- launch -----------------------------------------------------
extern "C" void kernel_launch(void* const* d_in, const int* in_sizes, int n_in,
                              void* d_out, int out_size) {
    const float* outputs = (const float*)d_in[0];
    const float* labels  = (const float*)d_in[1];
    const float* tmask   = (const float*)d_in[2];
    float* out = (float*)d_out;

    zero_kernel<<<NINST, 256>>>();
    pass0_kernel<<<dim3(100, NINST), 256>>>(outputs, labels, tmask);
    select_kernel<<<NINST, 256>>>(0);
    hist_kernel<<<dim3(100, NINST), 256>>>(16);
    select_kernel<<<NINST, 256>>>(1);
    hist_kernel<<<dim3(100, NINST), 256>>>(8);
    select_kernel<<<NINST, 256>>>(2);
    hist_kernel<<<dim3(100, NINST), 256>>>(0);
    select_kernel<<<NINST, 256>>>(3);
    dice_kernel<<<dim3(100, NINST), 256>>>(outputs, labels, tmask);
    finalize_kernel<<<1, 32>>>(out);
}